// round 14
// baseline (speedup 1.0000x reference)
#include <cuda_runtime.h>
#include <cstdint>
#include <math.h>

#define BATCH 64
#define CCH   512
#define NPIX  1024
#define DD    64

// ---------------- scratch (static device arrays) ----------------
__device__ __align__(128) float g_q [BATCH * CCH * DD];
__device__ __align__(128) float g_k [BATCH * CCH * DD];
__device__ __align__(128) float g_at[(size_t)BATCH * CCH * CCH]; // unnormalized T, tf32
__device__ __align__(128) float g_m [(size_t)BATCH * CCH * CCH]; // M, tf32
__device__ __align__(128) float g_ab[BATCH * CCH];               // (T.b)/S per (b,j)
__device__ __align__(128) float g_inv[BATCH * CCH];              // 1/S per (b,j)
__device__ __align__(128) float g_ps [BATCH * CCH * 8];          // partial col sums
__device__ __align__(128) float g_psb[BATCH * CCH * 8];          // partial col bias dots
__device__ __align__(128) float g_wt[CCH * CCH];                 // W^T, tf32
__device__ __align__(128) float g_xt[(size_t)BATCH * NPIX * CCH];// x^T, tf32
__device__ __align__(128) float g_bt[128 * NPIX];                // [Qm^T;Km^T] raw fp32

// ---------------- helpers ----------------
__device__ __forceinline__ float to_tf32(float x) {
    uint32_t u;
    asm("cvt.rna.tf32.f32 %0, %1;" : "=r"(u) : "f"(x));
    return __uint_as_float(u);
}
__device__ __forceinline__ void split_tf32(float v, uint32_t& h, uint32_t& l) {
    uint32_t u;
    asm("cvt.rna.tf32.f32 %0, %1;" : "=r"(u) : "f"(v));
    h = u;
    l = __float_as_uint(v - __uint_as_float(u));
}
__device__ __forceinline__ uint32_t smem_u32(const void* p) {
    uint32_t a;
    asm("{ .reg .u64 t; cvta.to.shared.u64 t, %1; cvt.u32.u64 %0, t; }" : "=r"(a) : "l"(p));
    return a;
}
__device__ __forceinline__ void cpa16(uint32_t d, const void* g) {
    asm volatile("cp.async.cg.shared.global [%0], [%1], 16;" :: "r"(d), "l"(g) : "memory");
}
__device__ __forceinline__ void cpa_commit() {
    asm volatile("cp.async.commit_group;" ::: "memory");
}
__device__ __forceinline__ void mma_tf32(float* c, const uint32_t* a, const uint32_t* b) {
    asm volatile(
        "mma.sync.aligned.m16n8k8.row.col.f32.tf32.tf32.f32 "
        "{%0,%1,%2,%3}, {%4,%5,%6,%7}, {%8,%9}, {%0,%1,%2,%3};"
        : "+f"(c[0]), "+f"(c[1]), "+f"(c[2]), "+f"(c[3])
        : "r"(a[0]), "r"(a[1]), "r"(a[2]), "r"(a[3]), "r"(b[0]), "r"(b[1]));
}

// ============================================================================
// prep_b: g_bt[d'][n] raw fp32: d'<64 -> Qm[n][d'], else Km[n][d'-64]
// ============================================================================
__global__ __launch_bounds__(256) void prep_b(
    const float* __restrict__ qm, const float* __restrict__ km)
{
    const int n = blockIdx.x * 256 + threadIdx.x;
    const int d = blockIdx.y;
    g_bt[d * NPIX + n] = (d < 64) ? qm[n * 64 + d] : km[n * 64 + (d - 64)];
}

// ============================================================================
// qk3x v2: [q|k] = x @ [Qm|Km] via 3xTF32 MMA with IN-REGISTER hi/lo split.
// Raw fp32 A,B planes in smem (cp.async both), 64KB total -> 2 CTAs/SM.
// Tile 128(c) x 128(d'), BK=32. grid (4, BATCH).
// ============================================================================
__global__ __launch_bounds__(256, 2) void qk3x_kernel(const float* __restrict__ x)
{
    extern __shared__ __align__(16) float qs[];
    // per buffer (floats): A[0,4096) B[4096,8192); buffer stride 8192
    const int b = blockIdx.y;
    const int row0 = blockIdx.x * 128;
    const float* Ab = x + (size_t)b * CCH * NPIX + (size_t)row0 * NPIX;

    const int tid = threadIdx.x;
    const int wid = tid >> 5, lid = tid & 31;
    const int gid = lid >> 2, tig = lid & 3;
    const int wm = wid >> 2, wn = wid & 3;

    const uint32_t sb = smem_u32(qs);
    const int ldrow = tid >> 3, ldch = tid & 7;
    const uint32_t sw = (uint32_t)((ldrow * 32 + ((ldch ^ (ldrow & 7)) << 2)) * 4);

    auto issue = [&](int s, int buf) {
        const int k0 = s * 32;
        const uint32_t abase = sb + buf * 32768 + sw;
        const uint32_t bbase = abase + 16384;
#pragma unroll
        for (int q = 0; q < 4; q++) {
            const int row = ldrow + q * 32;
            cpa16(abase + q * 4096, &Ab[(size_t)row * NPIX + k0 + ldch * 4]);
            cpa16(bbase + q * 4096, &g_bt[row * NPIX + k0 + ldch * 4]);
        }
        cpa_commit();
    };

    float acc[4][4][4] = {};
    int mrow[4], ncol[4];
#pragma unroll
    for (int i = 0; i < 4; i++) {
        mrow[i] = wm * 64 + i * 16 + gid;
        ncol[i] = wn * 32 + i * 8 + gid;
    }

    issue(0, 0);

    for (int s = 0; s < 32; s++) {
        const int buf = s & 1;
        if (s < 31) issue(s + 1, buf ^ 1);
        if (s < 31) { asm volatile("cp.async.wait_group 1;" ::: "memory"); }
        else        { asm volatile("cp.async.wait_group 0;" ::: "memory"); }
        __syncthreads();

        const float* as = qs + buf * 8192;
        const float* bs = as + 4096;
#pragma unroll
        for (int kk = 0; kk < 4; kk++) {
            const int c0 = 2 * kk, c1 = 2 * kk + 1;
            uint32_t ah[4][4], al[4][4];
#pragma unroll
            for (int mi = 0; mi < 4; mi++) {
                const int r1 = mrow[mi], r2 = r1 + 8;
                split_tf32(as[r1 * 32 + ((c0 ^ (r1 & 7)) << 2) + tig], ah[mi][0], al[mi][0]);
                split_tf32(as[r2 * 32 + ((c0 ^ (r2 & 7)) << 2) + tig], ah[mi][1], al[mi][1]);
                split_tf32(as[r1 * 32 + ((c1 ^ (r1 & 7)) << 2) + tig], ah[mi][2], al[mi][2]);
                split_tf32(as[r2 * 32 + ((c1 ^ (r2 & 7)) << 2) + tig], ah[mi][3], al[mi][3]);
            }
#pragma unroll
            for (int ni = 0; ni < 4; ni++) {
                const int cc = ncol[ni];
                uint32_t bh[2], bl[2];
                split_tf32(bs[cc * 32 + ((c0 ^ (cc & 7)) << 2) + tig], bh[0], bl[0]);
                split_tf32(bs[cc * 32 + ((c1 ^ (cc & 7)) << 2) + tig], bh[1], bl[1]);
#pragma unroll
                for (int mi = 0; mi < 4; mi++) {
                    mma_tf32(acc[mi][ni], ah[mi], bh);
                    mma_tf32(acc[mi][ni], ah[mi], bl);
                    mma_tf32(acc[mi][ni], al[mi], bh);
                }
            }
        }
        __syncthreads();
    }

    // epilogue: cols <64 -> g_q, >=64 -> g_k
#pragma unroll
    for (int mi = 0; mi < 4; mi++) {
        const int r1 = row0 + wm * 64 + mi * 16 + gid;
        const int r2 = r1 + 8;
#pragma unroll
        for (int ni = 0; ni < 4; ni++) {
            const int d = wn * 32 + ni * 8 + tig * 2;
            float* base = (d < 64) ? g_q : g_k;
            const int dc = d & 63;
            float* p1 = base + ((size_t)b * CCH + r1) * DD + dc;
            float* p2 = base + ((size_t)b * CCH + r2) * DD + dc;
            *(float2*)p1 = make_float2(acc[mi][ni][0], acc[mi][ni][1]);
            *(float2*)p2 = make_float2(acc[mi][ni][2], acc[mi][ni][3]);
        }
    }
}

// ============================================================================
// energy_mma: At[b][j][i] = tf32(T(e)), e = q.k^T via SINGLE-pass tf32 MMA.
// T = e>0 ? E : 1 (saturated); exact fp32 recompute when |e_approx| < 16.
// Tile 128(i) x 128(j), K=64 in smem. grid (4,4,64). 2 CTAs/SM.
// ============================================================================
#define E_CONST 2.71828182845904523536f

__global__ __launch_bounds__(256, 2) void energy_mma(const float* __restrict__ vb)
{
    extern __shared__ __align__(16) float es[];
    const int b  = blockIdx.z;
    const int j0 = blockIdx.x * 128;
    const int i0 = blockIdx.y * 128;
    const float* Q = g_q + ((size_t)b * CCH + i0) * DD;
    const float* K = g_k + ((size_t)b * CCH + j0) * DD;

    const int tid = threadIdx.x;
    const int wid = tid >> 5, lid = tid & 31;
    const int gid = lid >> 2, tig = lid & 3;
    const int wm = wid >> 2, wn = wid & 3;

#pragma unroll
    for (int t = 0; t < 8; t++) {
        const int idx = tid + t * 256;
        const int row = idx >> 4, ch = idx & 15;
        float4 v = *(const float4*)&Q[(size_t)row * DD + ch * 4];
        float4 h;
        h.x = to_tf32(v.x); h.y = to_tf32(v.y); h.z = to_tf32(v.z); h.w = to_tf32(v.w);
        *(float4*)&es[row * 64 + ((ch ^ (row & 7)) << 2)] = h;
        float4 w = *(const float4*)&K[(size_t)row * DD + ch * 4];
        float4 g;
        g.x = to_tf32(w.x); g.y = to_tf32(w.y); g.z = to_tf32(w.z); g.w = to_tf32(w.w);
        *(float4*)&es[8192 + row * 64 + ((ch ^ (row & 7)) << 2)] = g;
    }
    __syncthreads();

    float acc[4][4][4] = {};
    int mrow[4], ncol[4];
#pragma unroll
    for (int i = 0; i < 4; i++) {
        mrow[i] = wm * 64 + i * 16 + gid;
        ncol[i] = wn * 32 + i * 8 + gid;
    }

    const float* qsm = es;
    const float* ksm = es + 8192;
#pragma unroll
    for (int kk = 0; kk < 8; kk++) {
        const int c0 = 2 * kk, c1 = 2 * kk + 1;
        uint32_t af[4][4], bf[4][2];
#pragma unroll
        for (int mi = 0; mi < 4; mi++) {
            const int r1 = mrow[mi], r2 = r1 + 8;
            af[mi][0] = __float_as_uint(qsm[r1 * 64 + ((c0 ^ (r1 & 7)) << 2) + tig]);
            af[mi][1] = __float_as_uint(qsm[r2 * 64 + ((c0 ^ (r2 & 7)) << 2) + tig]);
            af[mi][2] = __float_as_uint(qsm[r1 * 64 + ((c1 ^ (r1 & 7)) << 2) + tig]);
            af[mi][3] = __float_as_uint(qsm[r2 * 64 + ((c1 ^ (r2 & 7)) << 2) + tig]);
        }
#pragma unroll
        for (int ni = 0; ni < 4; ni++) {
            const int cc = ncol[ni];
            bf[ni][0] = __float_as_uint(ksm[cc * 64 + ((c0 ^ (cc & 7)) << 2) + tig]);
            bf[ni][1] = __float_as_uint(ksm[cc * 64 + ((c1 ^ (cc & 7)) << 2) + tig]);
        }
#pragma unroll
        for (int mi = 0; mi < 4; mi++)
#pragma unroll
            for (int ni = 0; ni < 4; ni++)
                mma_tf32(acc[mi][ni], af[mi], bf[ni]);
    }

    auto xf = [&](float e, int gi, int gj) -> float {
        if (fabsf(e) < 16.0f) {
            const float* qr = g_q + ((size_t)b * CCH + gi) * DD;
            const float* kr = g_k + ((size_t)b * CCH + gj) * DD;
            float s = 0.0f;
#pragma unroll
            for (int d = 0; d < DD; d += 4) {
                float4 a4 = *(const float4*)&qr[d];
                float4 b4 = *(const float4*)&kr[d];
                s += a4.x * b4.x + a4.y * b4.y + a4.z * b4.z + a4.w * b4.w;
            }
            float sg = 1.0f / (1.0f + __expf(-s));
            return __expf(sg);
        }
        return (e > 0.0f) ? E_CONST : 1.0f;
    };
#pragma unroll
    for (int mi = 0; mi < 4; mi++) {
        const int r1 = mrow[mi], r2 = r1 + 8;
#pragma unroll
        for (int ni = 0; ni < 4; ni++) {
            const int cc = wn * 32 + ni * 8 + tig * 2;
            acc[mi][ni][0] = to_tf32(xf(acc[mi][ni][0], i0 + r1, j0 + cc));
            acc[mi][ni][1] = to_tf32(xf(acc[mi][ni][1], i0 + r1, j0 + cc + 1));
            acc[mi][ni][2] = to_tf32(xf(acc[mi][ni][2], i0 + r2, j0 + cc));
            acc[mi][ni][3] = to_tf32(xf(acc[mi][ni][3], i0 + r2, j0 + cc + 1));
        }
    }

    __syncthreads();
#pragma unroll
    for (int mi = 0; mi < 4; mi++) {
        const int r1 = mrow[mi], r2 = r1 + 8;
#pragma unroll
        for (int ni = 0; ni < 4; ni++) {
            const int cc = wn * 32 + ni * 8 + tig * 2;
            es[(cc + 0) * 132 + r1] = acc[mi][ni][0];
            es[(cc + 1) * 132 + r1] = acc[mi][ni][1];
            es[(cc + 0) * 132 + r2] = acc[mi][ni][2];
            es[(cc + 1) * 132 + r2] = acc[mi][ni][3];
        }
    }
    __syncthreads();

    const int jj = tid >> 1;
    const int half = (tid & 1) * 64;
    float* dst = g_at + ((size_t)b * CCH + j0 + jj) * CCH + i0 + half;
    float s = 0.0f, sb2 = 0.0f;
#pragma unroll
    for (int w = 0; w < 16; w++) {
        float4 v4 = *(float4*)&es[jj * 132 + half + w * 4];
        const float* bb = &vb[i0 + half + w * 4];
        s   += v4.x + v4.y + v4.z + v4.w;
        sb2 += v4.x * bb[0] + v4.y * bb[1] + v4.z * bb[2] + v4.w * bb[3];
        *(float4*)&dst[w * 4] = v4;
    }
    s   += __shfl_xor_sync(0xffffffffu, s,   1);
    sb2 += __shfl_xor_sync(0xffffffffu, sb2, 1);
    if ((tid & 1) == 0) {
        const int idx = ((b << 9) + j0 + jj) * 4 + blockIdx.y;
        g_ps[idx]  = s;
        g_psb[idx] = sb2;
    }
}

// ============================================================================
// reduce: S, TB -> g_inv = 1/S, g_ab = TB/S   (4 partials per row)
// ============================================================================
__global__ __launch_bounds__(256) void reduce_kernel()
{
    const int idx = blockIdx.x * 256 + threadIdx.x;
    float S = 0.0f, TB = 0.0f;
#pragma unroll
    for (int r = 0; r < 4; r++) { S += g_ps[idx * 4 + r]; TB += g_psb[idx * 4 + r]; }
    g_inv[idx] = 1.0f / S;
    g_ab[idx]  = TB / S;
}

// ============================================================================
// Transposes
// ============================================================================
__global__ __launch_bounds__(256) void wt_kernel(const float* __restrict__ W)
{
    __shared__ float t[32][33];
    const int x0 = blockIdx.x * 32, y0 = blockIdx.y * 32;
    const int tx = threadIdx.x, ty = threadIdx.y;
#pragma unroll
    for (int r = 0; r < 32; r += 8) t[ty + r][tx] = W[(y0 + ty + r) * CCH + x0 + tx];
    __syncthreads();
#pragma unroll
    for (int r = 0; r < 32; r += 8)
        g_wt[(x0 + ty + r) * CCH + y0 + tx] = to_tf32(t[tx][ty + r]);
}

__global__ __launch_bounds__(256) void xt_kernel(const float* __restrict__ x)
{
    __shared__ float t[32][33];
    const int b = blockIdx.z;
    const float* in = x + (size_t)b * CCH * NPIX;
    float* out = g_xt + (size_t)b * NPIX * CCH;
    const int n0 = blockIdx.x * 32, c0 = blockIdx.y * 32;
    const int tx = threadIdx.x, ty = threadIdx.y;
#pragma unroll
    for (int r = 0; r < 32; r += 8) t[ty + r][tx] = in[(size_t)(c0 + ty + r) * NPIX + n0 + tx];
    __syncthreads();
#pragma unroll
    for (int r = 0; r < 32; r += 8)
        out[(size_t)(n0 + ty + r) * CCH + c0 + tx] = to_tf32(t[tx][ty + r]);
}

// ============================================================================
// gemm_mma: R5-proven. 128x128, BK=32, double buffer, 2 CTA/SM.
// which==0: M = (At @ Wt) * (1/S_j), tf32 -> g_m
// which==1: out = M @ xT + ab
// ============================================================================
__global__ __launch_bounds__(256, 2) void gemm_mma(int which, float* __restrict__ outp)
{
    extern __shared__ __align__(16) float sm[];

    const int b = blockIdx.z;
    const int col0 = blockIdx.x * 128, row0 = blockIdx.y * 128;

    const float* A; const float* B; float* C; int ldc;
    if (which == 0) {
        A = g_at + (size_t)b * CCH * CCH;
        B = g_wt;
        C = g_m + (size_t)b * CCH * CCH;
        ldc = CCH;
    } else {
        A = g_m + (size_t)b * CCH * CCH;
        B = g_xt + (size_t)b * NPIX * CCH;
        C = outp + (size_t)b * CCH * NPIX;
        ldc = NPIX;
    }
    const float* Ab = A + (size_t)row0 * CCH;
    const float* Bb = B + (size_t)col0 * CCH;

    const int tid = threadIdx.x;
    const int wid = tid >> 5, lid = tid & 31;
    const int gid = lid >> 2, tig = lid & 3;
    const int wm = wid >> 2, wn = wid & 3;

    const uint32_t sb = smem_u32(sm);
    const int ldrow = tid >> 3, ldch = tid & 7;
    const uint32_t sw = (uint32_t)((ldrow * 32 + (((ldch) ^ (ldrow & 7)) << 2)) * 4);

    auto issue = [&](int s, int buf) {
        const int k0 = s * 32;
        const uint32_t abase = sb + buf * 16384 + sw;
        const uint32_t bbase = sb + 32768 + buf * 16384 + sw;
#pragma unroll
        for (int q = 0; q < 4; q++) {
            int row = ldrow + q * 32;
            cpa16(abase + q * 32 * 128, &Ab[(size_t)row * CCH + k0 + ldch * 4]);
            cpa16(bbase + q * 32 * 128, &Bb[(size_t)row * CCH + k0 + ldch * 4]);
        }
        cpa_commit();
    };

    float acc[4][4][4] = {};
    int mrow[4], ncol[4];
#pragma unroll
    for (int i = 0; i < 4; i++) {
        mrow[i] = wm * 64 + i * 16 + gid;
        ncol[i] = wn * 32 + i * 8 + gid;
    }

    issue(0, 0);

    for (int s = 0; s < 16; s++) {
        const int buf = s & 1;
        if (s < 15) issue(s + 1, buf ^ 1);
        if (s < 15) { asm volatile("cp.async.wait_group 1;" ::: "memory"); }
        else        { asm volatile("cp.async.wait_group 0;" ::: "memory"); }
        __syncthreads();

        const float* as = sm + buf * 4096;
        const float* bs = sm + 8192 + buf * 4096;
#pragma unroll
        for (int kk = 0; kk < 4; kk++) {
            const int c0ch = 2 * kk, c1ch = 2 * kk + 1;
            uint32_t af[4][4], bf[4][2];
#pragma unroll
            for (int mi = 0; mi < 4; mi++) {
                const int r1 = mrow[mi], r2 = r1 + 8;
                af[mi][0] = __float_as_uint(as[r1 * 32 + ((c0ch ^ (r1 & 7)) << 2) + tig]);
                af[mi][1] = __float_as_uint(as[r2 * 32 + ((c0ch ^ (r2 & 7)) << 2) + tig]);
                af[mi][2] = __float_as_uint(as[r1 * 32 + ((c1ch ^ (r1 & 7)) << 2) + tig]);
                af[mi][3] = __float_as_uint(as[r2 * 32 + ((c1ch ^ (r2 & 7)) << 2) + tig]);
            }
#pragma unroll
            for (int ni = 0; ni < 4; ni++) {
                const int cc = ncol[ni];
                bf[ni][0] = __float_as_uint(bs[cc * 32 + ((c0ch ^ (cc & 7)) << 2) + tig]);
                bf[ni][1] = __float_as_uint(bs[cc * 32 + ((c1ch ^ (cc & 7)) << 2) + tig]);
            }
#pragma unroll
            for (int mi = 0; mi < 4; mi++)
#pragma unroll
                for (int ni = 0; ni < 4; ni++)
                    mma_tf32(acc[mi][ni], af[mi], bf[ni]);
        }
        __syncthreads();
    }

#pragma unroll
    for (int mi = 0; mi < 4; mi++) {
        const int r1 = row0 + wm * 64 + mi * 16 + gid;
        const int r2 = r1 + 8;
        float s1, s2;
        if (which == 0) { s1 = g_inv[(b << 9) + r1]; s2 = g_inv[(b << 9) + r2]; }
        else            { s1 = g_ab [(b << 9) + r1]; s2 = g_ab [(b << 9) + r2]; }
#pragma unroll
        for (int ni = 0; ni < 4; ni++) {
            const int cc = col0 + wn * 32 + ni * 8 + tig * 2;
            float* p1 = &C[(size_t)r1 * ldc + cc];
            float* p2 = &C[(size_t)r2 * ldc + cc];
            float c0 = acc[mi][ni][0], c1 = acc[mi][ni][1];
            float c2 = acc[mi][ni][2], c3 = acc[mi][ni][3];
            if (which == 0) {
                c0 = to_tf32(c0 * s1); c1 = to_tf32(c1 * s1);
                c2 = to_tf32(c2 * s2); c3 = to_tf32(c3 * s2);
            } else {
                c0 += s1; c1 += s1; c2 += s2; c3 += s2;
            }
            *(float2*)p1 = make_float2(c0, c1);
            *(float2*)p2 = make_float2(c2, c3);
        }
    }
}

// ============================================================================
// kernel_launch: forked-stream capture (wt, xt on side stream).
// ============================================================================
extern "C" void kernel_launch(void* const* d_in, const int* in_sizes, int n_in,
                              void* d_out, int out_size)
{
    const float* x  = (const float*)d_in[0];
    const float* qm = (const float*)d_in[1];
    const float* km = (const float*)d_in[2];
    const float* vw = (const float*)d_in[3];
    const float* vb = (const float*)d_in[4];
    float* out = (float*)d_out;

    cudaFuncSetAttribute(gemm_mma,    cudaFuncAttributeMaxDynamicSharedMemorySize, 65536);
    cudaFuncSetAttribute(qk3x_kernel, cudaFuncAttributeMaxDynamicSharedMemorySize, 65536);
    cudaFuncSetAttribute(energy_mma,  cudaFuncAttributeMaxDynamicSharedMemorySize, 67584);

    cudaStream_t s1;
    cudaEvent_t eFork, eJoin;
    cudaStreamCreateWithFlags(&s1, cudaStreamNonBlocking);
    cudaEventCreateWithFlags(&eFork, cudaEventDisableTiming);
    cudaEventCreateWithFlags(&eJoin, cudaEventDisableTiming);

    cudaEventRecord(eFork, 0);
    cudaStreamWaitEvent(s1, eFork, 0);
    wt_kernel<<<dim3(16, 16),        dim3(32, 8), 0, s1>>>(vw);
    xt_kernel<<<dim3(32, 16, BATCH), dim3(32, 8), 0, s1>>>(x);
    cudaEventRecord(eJoin, s1);

    prep_b       <<<dim3(NPIX / 256, 128),       256>>>(qm, km);
    qk3x_kernel  <<<dim3(4, BATCH),              256, 65536>>>(x);
    energy_mma   <<<dim3(4, 4, BATCH),           256, 67584>>>(vb);
    reduce_kernel<<<dim3(BATCH * CCH / 256),     256>>>();

    cudaStreamWaitEvent(0, eJoin, 0);
    gemm_mma<<<dim3(CCH / 128,  CCH / 128, BATCH), 256, 65536>>>(0, nullptr);
    gemm_mma<<<dim3(NPIX / 128, CCH / 128, BATCH), 256, 65536>>>(1, out);
}

// round 15
// speedup vs baseline: 1.2731x; 1.2731x over previous
#include <cuda_runtime.h>
#include <cuda_fp16.h>
#include <cstdint>
#include <math.h>

#define BATCH 64
#define CCH   512
#define NPIX  1024
#define DD    64

// ---------------- scratch ----------------
__device__ __align__(128) float  g_q [BATCH * CCH * DD];
__device__ __align__(128) float  g_k [BATCH * CCH * DD];
__device__ __align__(128) __half g_at_h[(size_t)BATCH * CCH * CCH]; // unnorm T, half
__device__ __align__(128) __half g_m_h [(size_t)BATCH * CCH * CCH]; // M, half
__device__ __align__(128) float  g_ab[BATCH * CCH];
__device__ __align__(128) float  g_inv[BATCH * CCH];
__device__ __align__(128) float  g_ps [BATCH * CCH * 4];
__device__ __align__(128) float  g_psb[BATCH * CCH * 4];
__device__ __align__(128) __half g_wt_h[CCH * CCH];                  // W^T half
__device__ __align__(128) __half g_xt_h[(size_t)BATCH * NPIX * CCH]; // x^T half
__device__ __align__(128) __half g_bhi_h[128 * NPIX];                // [Qm^T;Km^T] hi
__device__ __align__(128) __half g_blo_h[128 * NPIX];                // lo

// ---------------- helpers ----------------
__device__ __forceinline__ uint32_t smem_u32(const void* p) {
    uint32_t a;
    asm("{ .reg .u64 t; cvta.to.shared.u64 t, %1; cvt.u32.u64 %0, t; }" : "=r"(a) : "l"(p));
    return a;
}
__device__ __forceinline__ void cpa16(uint32_t d, const void* g) {
    asm volatile("cp.async.cg.shared.global [%0], [%1], 16;" :: "r"(d), "l"(g) : "memory");
}
__device__ __forceinline__ void cpa_commit() {
    asm volatile("cp.async.commit_group;" ::: "memory");
}
__device__ __forceinline__ void mma_f16(float* c, const uint32_t* a, const uint32_t* b) {
    asm volatile(
        "mma.sync.aligned.m16n8k16.row.col.f32.f16.f16.f32 "
        "{%0,%1,%2,%3}, {%4,%5,%6,%7}, {%8,%9}, {%0,%1,%2,%3};"
        : "+f"(c[0]), "+f"(c[1]), "+f"(c[2]), "+f"(c[3])
        : "r"(a[0]), "r"(a[1]), "r"(a[2]), "r"(a[3]), "r"(b[0]), "r"(b[1]));
}
__device__ __forceinline__ uint32_t pack2(__half a, __half b) {
    __half2 t = __halves2half2(a, b);
    return *reinterpret_cast<uint32_t*>(&t);
}
__device__ __forceinline__ uint32_t ldsm32(const __half* p) {
    return *reinterpret_cast<const uint32_t*>(p);
}

// ============================================================================
// prep_b: half hi/lo planes of [Qm^T; Km^T]
// ============================================================================
__global__ __launch_bounds__(256) void prep_b(
    const float* __restrict__ qm, const float* __restrict__ km)
{
    const int n = blockIdx.x * 256 + threadIdx.x;
    const int d = blockIdx.y;
    float v = (d < 64) ? qm[n * 64 + d] : km[n * 64 + (d - 64)];
    __half h = __float2half_rn(v);
    g_bhi_h[d * NPIX + n] = h;
    g_blo_h[d * NPIX + n] = __float2half_rn(v - __half2float(h));
}

// ============================================================================
// qk3x fp16: [q|k] = x @ [Qm|Km], 3-pass hi/lo f16 MMA, BK=32 halves.
// smem/buffer: Ah[128x32]h Al Bh Bl (8KB each) = 32KB; x2 = 64KB; 2 CTA/SM.
// Row = 64B = 4 chunks; swizzle ch ^ ((row>>1)&3). grid (4, BATCH).
// ============================================================================
__global__ __launch_bounds__(256, 2) void qk3x_kernel(const float* __restrict__ x)
{
    extern __shared__ __align__(16) __half qs[];
    const int b = blockIdx.y;
    const int row0 = blockIdx.x * 128;
    const float* Ab = x + (size_t)b * CCH * NPIX + (size_t)row0 * NPIX;

    const int tid = threadIdx.x;
    const int wid = tid >> 5, lid = tid & 31;
    const int gid = lid >> 2, tig = lid & 3;
    const int wm = wid >> 2, wn = wid & 3;

    const uint32_t sb = smem_u32(qs);
    const int row_st = tid >> 1, hh = tid & 1;
    const int asw = (row_st >> 1) & 3;

    float4 va[4];
    auto ldgA = [&](int s) {
        const int k0 = s * 32;
#pragma unroll
        for (int q = 0; q < 4; q++)
            va[q] = *(const float4*)&Ab[(size_t)row_st * NPIX + k0 + hh * 16 + q * 4];
    };
    auto stsA = [&](int buf) {
        __half hv[16], lv[16];
#pragma unroll
        for (int q = 0; q < 4; q++) {
            const float f[4] = {va[q].x, va[q].y, va[q].z, va[q].w};
#pragma unroll
            for (int c = 0; c < 4; c++) {
                __half h = __float2half_rn(f[c]);
                hv[q * 4 + c] = h;
                lv[q * 4 + c] = __float2half_rn(f[c] - __half2float(h));
            }
        }
        const int base = buf * 16384 + row_st * 32;
        const int c0 = (2 * hh) ^ asw, c1 = (2 * hh + 1) ^ asw;
        *(uint4*)&qs[base + c0 * 8] = make_uint4(
            pack2(hv[0], hv[1]), pack2(hv[2], hv[3]), pack2(hv[4], hv[5]), pack2(hv[6], hv[7]));
        *(uint4*)&qs[base + c1 * 8] = make_uint4(
            pack2(hv[8], hv[9]), pack2(hv[10], hv[11]), pack2(hv[12], hv[13]), pack2(hv[14], hv[15]));
        *(uint4*)&qs[base + 4096 + c0 * 8] = make_uint4(
            pack2(lv[0], lv[1]), pack2(lv[2], lv[3]), pack2(lv[4], lv[5]), pack2(lv[6], lv[7]));
        *(uint4*)&qs[base + 4096 + c1 * 8] = make_uint4(
            pack2(lv[8], lv[9]), pack2(lv[10], lv[11]), pack2(lv[12], lv[13]), pack2(lv[14], lv[15]));
    };
    auto cpaB = [&](int s, int buf) {
        const int k0 = s * 32;
        const int c2 = hh * 2;
#pragma unroll
        for (int p = 0; p < 2; p++) {
            const int off = (p == 0) ? 8192 : 12288;
            const __half* src = (p == 0) ? g_bhi_h : g_blo_h;
#pragma unroll
            for (int ci = 0; ci < 2; ci++) {
                const int c = c2 + ci;
                const int cs = c ^ asw;
                cpa16(sb + (uint32_t)(buf * 16384 + off + row_st * 32 + cs * 8) * 2,
                      src + row_st * NPIX + k0 + c * 8);
            }
        }
        cpa_commit();
    };

    float acc[4][4][4] = {};
    int mrow[4], ncol[4];
#pragma unroll
    for (int i = 0; i < 4; i++) {
        mrow[i] = wm * 64 + i * 16 + gid;
        ncol[i] = wn * 32 + i * 8 + gid;
    }

    ldgA(0);
    cpaB(0, 0);
    stsA(0);

    for (int s = 0; s < 32; s++) {
        const int buf = s & 1;
        asm volatile("cp.async.wait_group 0;" ::: "memory");
        __syncthreads();
        if (s < 31) { ldgA(s + 1); cpaB(s + 1, buf ^ 1); }

        const __half* Ah = qs + buf * 16384;
        const __half* Al = Ah + 4096;
        const __half* Bh = Ah + 8192;
        const __half* Bl = Ah + 12288;
#pragma unroll
        for (int ks = 0; ks < 2; ks++) {
            uint32_t ah[4][4], al[4][4];
#pragma unroll
            for (int mi = 0; mi < 4; mi++) {
                const int r1 = mrow[mi], r2 = r1 + 8;
                const int s1 = (r1 >> 1) & 3, s2 = (r2 >> 1) & 3;
                const int i00 = r1 * 32 + ((2 * ks) ^ s1) * 8 + 2 * tig;
                const int i10 = r2 * 32 + ((2 * ks) ^ s2) * 8 + 2 * tig;
                const int i01 = r1 * 32 + ((2 * ks + 1) ^ s1) * 8 + 2 * tig;
                const int i11 = r2 * 32 + ((2 * ks + 1) ^ s2) * 8 + 2 * tig;
                ah[mi][0] = ldsm32(Ah + i00); ah[mi][1] = ldsm32(Ah + i10);
                ah[mi][2] = ldsm32(Ah + i01); ah[mi][3] = ldsm32(Ah + i11);
                al[mi][0] = ldsm32(Al + i00); al[mi][1] = ldsm32(Al + i10);
                al[mi][2] = ldsm32(Al + i01); al[mi][3] = ldsm32(Al + i11);
            }
#pragma unroll
            for (int ni = 0; ni < 4; ni++) {
                const int cc = ncol[ni];
                const int sc = (cc >> 1) & 3;
                const int j0i = cc * 32 + ((2 * ks) ^ sc) * 8 + 2 * tig;
                const int j1i = cc * 32 + ((2 * ks + 1) ^ sc) * 8 + 2 * tig;
                uint32_t bh[2] = {ldsm32(Bh + j0i), ldsm32(Bh + j1i)};
                uint32_t bl[2] = {ldsm32(Bl + j0i), ldsm32(Bl + j1i)};
#pragma unroll
                for (int mi = 0; mi < 4; mi++) {
                    mma_f16(acc[mi][ni], ah[mi], bh);
                    mma_f16(acc[mi][ni], ah[mi], bl);
                    mma_f16(acc[mi][ni], al[mi], bh);
                }
            }
        }
        __syncthreads();
        if (s < 31) stsA(buf ^ 1);
    }

    // epilogue: cols <64 -> g_q, >=64 -> g_k (fp32, needed for exact recompute)
#pragma unroll
    for (int mi = 0; mi < 4; mi++) {
        const int r1 = row0 + wm * 64 + mi * 16 + gid;
        const int r2 = r1 + 8;
#pragma unroll
        for (int ni = 0; ni < 4; ni++) {
            const int d = wn * 32 + ni * 8 + tig * 2;
            float* base = (d < 64) ? g_q : g_k;
            const int dc = d & 63;
            float* p1 = base + ((size_t)b * CCH + r1) * DD + dc;
            float* p2 = base + ((size_t)b * CCH + r2) * DD + dc;
            *(float2*)p1 = make_float2(acc[mi][ni][0], acc[mi][ni][1]);
            *(float2*)p2 = make_float2(acc[mi][ni][2], acc[mi][ni][3]);
        }
    }
}

// ============================================================================
// energy_mma fp16: single-pass f16 MMA; saturate; exact recompute |e|<16.
// q,k half [128][64] (128B rows, swizzle ch^(row&7)); staging float aliased.
// grid (4,4,64). smem 67584 B. 2 CTA/SM.
// ============================================================================
#define E_CONST 2.71828182845904523536f

__global__ __launch_bounds__(256, 2) void energy_mma(const float* __restrict__ vb)
{
    extern __shared__ __align__(16) float es[];
    __half* smh = (__half*)es;
    const int b  = blockIdx.z;
    const int j0 = blockIdx.x * 128;
    const int i0 = blockIdx.y * 128;
    const float* Q = g_q + ((size_t)b * CCH + i0) * DD;
    const float* K = g_k + ((size_t)b * CCH + j0) * DD;

    const int tid = threadIdx.x;
    const int wid = tid >> 5, lid = tid & 31;
    const int gid = lid >> 2, tig = lid & 3;
    const int wm = wid >> 2, wn = wid & 3;

    // load + convert q,k to half (32 values per thread per matrix)
    {
        const int row = tid >> 1, hh = tid & 1;
        const int rsw = row & 7;
#pragma unroll
        for (int m = 0; m < 2; m++) {
            const float* src = (m == 0) ? Q : K;
            __half* dst = smh + m * 8192;
            __half hv[32];
#pragma unroll
            for (int i = 0; i < 8; i++) {
                float4 v = *(const float4*)&src[(size_t)row * DD + hh * 32 + i * 4];
                hv[i * 4 + 0] = __float2half_rn(v.x);
                hv[i * 4 + 1] = __float2half_rn(v.y);
                hv[i * 4 + 2] = __float2half_rn(v.z);
                hv[i * 4 + 3] = __float2half_rn(v.w);
            }
#pragma unroll
            for (int i = 0; i < 4; i++) {
                const int c = hh * 4 + i;
                const int cs = c ^ rsw;
                *(uint4*)&dst[row * 64 + cs * 8] = make_uint4(
                    pack2(hv[i*8+0], hv[i*8+1]), pack2(hv[i*8+2], hv[i*8+3]),
                    pack2(hv[i*8+4], hv[i*8+5]), pack2(hv[i*8+6], hv[i*8+7]));
            }
        }
    }
    __syncthreads();

    float acc[4][4][4] = {};
    int mrow[4], ncol[4];
#pragma unroll
    for (int i = 0; i < 4; i++) {
        mrow[i] = wm * 64 + i * 16 + gid;
        ncol[i] = wn * 32 + i * 8 + gid;
    }

    const __half* qh = smh;
    const __half* kh = smh + 8192;
#pragma unroll
    for (int ks = 0; ks < 4; ks++) {
        uint32_t af[4][4], bf[4][2];
#pragma unroll
        for (int mi = 0; mi < 4; mi++) {
            const int r1 = mrow[mi], r2 = r1 + 8;
            af[mi][0] = ldsm32(qh + r1 * 64 + ((2*ks)   ^ (r1 & 7)) * 8 + 2 * tig);
            af[mi][1] = ldsm32(qh + r2 * 64 + ((2*ks)   ^ (r2 & 7)) * 8 + 2 * tig);
            af[mi][2] = ldsm32(qh + r1 * 64 + ((2*ks+1) ^ (r1 & 7)) * 8 + 2 * tig);
            af[mi][3] = ldsm32(qh + r2 * 64 + ((2*ks+1) ^ (r2 & 7)) * 8 + 2 * tig);
        }
#pragma unroll
        for (int ni = 0; ni < 4; ni++) {
            const int cc = ncol[ni];
            bf[ni][0] = ldsm32(kh + cc * 64 + ((2*ks)   ^ (cc & 7)) * 8 + 2 * tig);
            bf[ni][1] = ldsm32(kh + cc * 64 + ((2*ks+1) ^ (cc & 7)) * 8 + 2 * tig);
        }
#pragma unroll
        for (int mi = 0; mi < 4; mi++)
#pragma unroll
            for (int ni = 0; ni < 4; ni++)
                mma_f16(acc[mi][ni], af[mi], bf[ni]);
    }

    auto xf = [&](float e, int gi, int gj) -> float {
        if (fabsf(e) < 16.0f) {
            const float* qr = g_q + ((size_t)b * CCH + gi) * DD;
            const float* kr = g_k + ((size_t)b * CCH + gj) * DD;
            float s = 0.0f;
#pragma unroll
            for (int d = 0; d < DD; d += 4) {
                float4 a4 = *(const float4*)&qr[d];
                float4 b4 = *(const float4*)&kr[d];
                s += a4.x * b4.x + a4.y * b4.y + a4.z * b4.z + a4.w * b4.w;
            }
            float sg = 1.0f / (1.0f + __expf(-s));
            return __expf(sg);
        }
        return (e > 0.0f) ? E_CONST : 1.0f;
    };
#pragma unroll
    for (int mi = 0; mi < 4; mi++) {
        const int r1 = mrow[mi], r2 = r1 + 8;
#pragma unroll
        for (int ni = 0; ni < 4; ni++) {
            const int cc = wn * 32 + ni * 8 + tig * 2;
            acc[mi][ni][0] = xf(acc[mi][ni][0], i0 + r1, j0 + cc);
            acc[mi][ni][1] = xf(acc[mi][ni][1], i0 + r1, j0 + cc + 1);
            acc[mi][ni][2] = xf(acc[mi][ni][2], i0 + r2, j0 + cc);
            acc[mi][ni][3] = xf(acc[mi][ni][3], i0 + r2, j0 + cc + 1);
        }
    }

    __syncthreads();
#pragma unroll
    for (int mi = 0; mi < 4; mi++) {
        const int r1 = mrow[mi], r2 = r1 + 8;
#pragma unroll
        for (int ni = 0; ni < 4; ni++) {
            const int cc = wn * 32 + ni * 8 + tig * 2;
            es[(cc + 0) * 132 + r1] = acc[mi][ni][0];
            es[(cc + 1) * 132 + r1] = acc[mi][ni][1];
            es[(cc + 0) * 132 + r2] = acc[mi][ni][2];
            es[(cc + 1) * 132 + r2] = acc[mi][ni][3];
        }
    }
    __syncthreads();

    const int jj = tid >> 1;
    const int half_i = (tid & 1) * 64;
    __half* dst = g_at_h + ((size_t)b * CCH + j0 + jj) * CCH + i0 + half_i;
    float s = 0.0f, sb2 = 0.0f;
#pragma unroll
    for (int w = 0; w < 8; w++) {
        float4 v0 = *(float4*)&es[jj * 132 + half_i + w * 8];
        float4 v1 = *(float4*)&es[jj * 132 + half_i + w * 8 + 4];
        const float* bb = &vb[i0 + half_i + w * 8];
        s   += v0.x + v0.y + v0.z + v0.w + v1.x + v1.y + v1.z + v1.w;
        sb2 += v0.x*bb[0] + v0.y*bb[1] + v0.z*bb[2] + v0.w*bb[3]
             + v1.x*bb[4] + v1.y*bb[5] + v1.z*bb[6] + v1.w*bb[7];
        *(uint4*)&dst[w * 8] = make_uint4(
            pack2(__float2half_rn(v0.x), __float2half_rn(v0.y)),
            pack2(__float2half_rn(v0.z), __float2half_rn(v0.w)),
            pack2(__float2half_rn(v1.x), __float2half_rn(v1.y)),
            pack2(__float2half_rn(v1.z), __float2half_rn(v1.w)));
    }
    s   += __shfl_xor_sync(0xffffffffu, s,   1);
    sb2 += __shfl_xor_sync(0xffffffffu, sb2, 1);
    if ((tid & 1) == 0) {
        const int idx = ((b << 9) + j0 + jj) * 4 + blockIdx.y;
        g_ps[idx]  = s;
        g_psb[idx] = sb2;
    }
}

// ============================================================================
// reduce
// ============================================================================
__global__ __launch_bounds__(256) void reduce_kernel()
{
    const int idx = blockIdx.x * 256 + threadIdx.x;
    float S = 0.0f, TB = 0.0f;
#pragma unroll
    for (int r = 0; r < 4; r++) { S += g_ps[idx * 4 + r]; TB += g_psb[idx * 4 + r]; }
    g_inv[idx] = 1.0f / S;
    g_ab[idx]  = TB / S;
}

// ============================================================================
// Transposes (half outputs)
// ============================================================================
__global__ __launch_bounds__(256) void wt_kernel(const float* __restrict__ W)
{
    __shared__ float t[32][33];
    const int x0 = blockIdx.x * 32, y0 = blockIdx.y * 32;
    const int tx = threadIdx.x, ty = threadIdx.y;
#pragma unroll
    for (int r = 0; r < 32; r += 8) t[ty + r][tx] = W[(y0 + ty + r) * CCH + x0 + tx];
    __syncthreads();
#pragma unroll
    for (int r = 0; r < 32; r += 8)
        g_wt_h[(x0 + ty + r) * CCH + y0 + tx] = __float2half_rn(t[tx][ty + r]);
}

__global__ __launch_bounds__(256) void xt_kernel(const float* __restrict__ x)
{
    __shared__ float t[32][33];
    const int b = blockIdx.z;
    const float* in = x + (size_t)b * CCH * NPIX;
    __half* out = g_xt_h + (size_t)b * NPIX * CCH;
    const int n0 = blockIdx.x * 32, c0 = blockIdx.y * 32;
    const int tx = threadIdx.x, ty = threadIdx.y;
#pragma unroll
    for (int r = 0; r < 32; r += 8) t[ty + r][tx] = in[(size_t)(c0 + ty + r) * NPIX + n0 + tx];
    __syncthreads();
#pragma unroll
    for (int r = 0; r < 32; r += 8)
        out[(size_t)(n0 + ty + r) * CCH + c0 + tx] = __float2half_rn(t[tx][ty + r]);
}

// ============================================================================
// gemm fp16: 128x128 tile, BK=64 halves, double buffer (64KB), 2 CTA/SM.
// which==0: g_m_h = half((g_at_h @ g_wt_h) * (1/S_j))
// which==1: out   = (g_m_h @ g_xt_h) + ab     (fp32 out)
// ============================================================================
__global__ __launch_bounds__(256, 2) void gemm_f16(int which, float* __restrict__ outp)
{
    extern __shared__ __align__(16) __half sm[];

    const int b = blockIdx.z;
    const int col0 = blockIdx.x * 128, row0 = blockIdx.y * 128;

    const __half* A; const __half* B; __half* Ch = nullptr; float* Cf = nullptr; int ldc;
    if (which == 0) {
        A = g_at_h + (size_t)b * CCH * CCH;
        B = g_wt_h;
        Ch = g_m_h + (size_t)b * CCH * CCH;
        ldc = CCH;
    } else {
        A = g_m_h + (size_t)b * CCH * CCH;
        B = g_xt_h + (size_t)b * NPIX * CCH;
        Cf = outp + (size_t)b * CCH * NPIX;
        ldc = NPIX;
    }
    const __half* Ab = A + (size_t)row0 * CCH;
    const __half* Bb = B + (size_t)col0 * CCH;

    const int tid = threadIdx.x;
    const int wid = tid >> 5, lid = tid & 31;
    const int gid = lid >> 2, tig = lid & 3;
    const int wm = wid >> 2, wn = wid & 3;

    const uint32_t sb = smem_u32(sm);
    const int row_c = tid >> 1, hh = tid & 1;
    const int csw = row_c & 7;

    auto issue = [&](int s, int buf) {
        const int k0 = s * 64;
#pragma unroll
        for (int i = 0; i < 4; i++) {
            const int c = hh * 4 + i;
            const int cs = c ^ csw;
            cpa16(sb + (uint32_t)(buf * 16384 + row_c * 64 + cs * 8) * 2,
                  Ab + (size_t)row_c * CCH + k0 + c * 8);
            cpa16(sb + (uint32_t)(buf * 16384 + 8192 + row_c * 64 + cs * 8) * 2,
                  Bb + (size_t)row_c * CCH + k0 + c * 8);
        }
        cpa_commit();
    };

    float acc[4][4][4] = {};
    int mrow[4], ncol[4];
#pragma unroll
    for (int i = 0; i < 4; i++) {
        mrow[i] = wm * 64 + i * 16 + gid;
        ncol[i] = wn * 32 + i * 8 + gid;
    }

    issue(0, 0);

    for (int s = 0; s < 8; s++) {
        const int buf = s & 1;
        if (s < 7) issue(s + 1, buf ^ 1);
        if (s < 7) { asm volatile("cp.async.wait_group 1;" ::: "memory"); }
        else       { asm volatile("cp.async.wait_group 0;" ::: "memory"); }
        __syncthreads();

        const __half* as = sm + buf * 16384;
        const __half* bs = as + 8192;
#pragma unroll
        for (int ks = 0; ks < 4; ks++) {
            uint32_t af[4][4], bf[4][2];
#pragma unroll
            for (int mi = 0; mi < 4; mi++) {
                const int r1 = mrow[mi], r2 = r1 + 8;
                af[mi][0] = ldsm32(as + r1 * 64 + ((2*ks)   ^ (r1 & 7)) * 8 + 2 * tig);
                af[mi][1] = ldsm32(as + r2 * 64 + ((2*ks)   ^ (r2 & 7)) * 8 + 2 * tig);
                af[mi][2] = ldsm32(as + r1 * 64 + ((2*ks+1) ^ (r1 & 7)) * 8 + 2 * tig);
                af[mi][3] = ldsm32(as + r2 * 64 + ((2*ks+1) ^ (r2 & 7)) * 8 + 2 * tig);
            }
#pragma unroll
            for (int ni = 0; ni < 4; ni++) {
                const int cc = ncol[ni];
                bf[ni][0] = ldsm32(bs + cc * 64 + ((2*ks)   ^ (cc & 7)) * 8 + 2 * tig);
                bf[ni][1] = ldsm32(bs + cc * 64 + ((2*ks+1) ^ (cc & 7)) * 8 + 2 * tig);
            }
#pragma unroll
            for (int mi = 0; mi < 4; mi++)
#pragma unroll
                for (int ni = 0; ni < 4; ni++)
                    mma_f16(acc[mi][ni], af[mi], bf[ni]);
        }
        __syncthreads();
    }

    // epilogue
#pragma unroll
    for (int mi = 0; mi < 4; mi++) {
        const int r1 = row0 + wm * 64 + mi * 16 + gid;
        const int r2 = r1 + 8;
        float s1, s2;
        if (which == 0) { s1 = g_inv[(b << 9) + r1]; s2 = g_inv[(b << 9) + r2]; }
        else            { s1 = g_ab [(b << 9) + r1]; s2 = g_ab [(b << 9) + r2]; }
#pragma unroll
        for (int ni = 0; ni < 4; ni++) {
            const int cc = col0 + wn * 32 + ni * 8 + tig * 2;
            float c0 = acc[mi][ni][0], c1 = acc[mi][ni][1];
            float c2 = acc[mi][ni][2], c3 = acc[mi][ni][3];
            if (which == 0) {
                *(uint32_t*)&Ch[(size_t)r1 * ldc + cc] =
                    pack2(__float2half_rn(c0 * s1), __float2half_rn(c1 * s1));
                *(uint32_t*)&Ch[(size_t)r2 * ldc + cc] =
                    pack2(__float2half_rn(c2 * s2), __float2half_rn(c3 * s2));
            } else {
                *(float2*)&Cf[(size_t)r1 * ldc + cc] = make_float2(c0 + s1, c1 + s1);
                *(float2*)&Cf[(size_t)r2 * ldc + cc] = make_float2(c2 + s2, c3 + s2);
            }
        }
    }
}

// ============================================================================
// kernel_launch: forked-stream capture (wt, xt on side stream).
// ============================================================================
extern "C" void kernel_launch(void* const* d_in, const int* in_sizes, int n_in,
                              void* d_out, int out_size)
{
    const float* x  = (const float*)d_in[0];
    const float* qm = (const float*)d_in[1];
    const float* km = (const float*)d_in[2];
    const float* vw = (const float*)d_in[3];
    const float* vb = (const float*)d_in[4];
    float* out = (float*)d_out;

    cudaFuncSetAttribute(gemm_f16,    cudaFuncAttributeMaxDynamicSharedMemorySize, 65536);
    cudaFuncSetAttribute(qk3x_kernel, cudaFuncAttributeMaxDynamicSharedMemorySize, 65536);
    cudaFuncSetAttribute(energy_mma,  cudaFuncAttributeMaxDynamicSharedMemorySize, 67584);

    cudaStream_t s1;
    cudaEvent_t eFork, eJoin;
    cudaStreamCreateWithFlags(&s1, cudaStreamNonBlocking);
    cudaEventCreateWithFlags(&eFork, cudaEventDisableTiming);
    cudaEventCreateWithFlags(&eJoin, cudaEventDisableTiming);

    cudaEventRecord(eFork, 0);
    cudaStreamWaitEvent(s1, eFork, 0);
    wt_kernel<<<dim3(16, 16),        dim3(32, 8), 0, s1>>>(vw);
    xt_kernel<<<dim3(32, 16, BATCH), dim3(32, 8), 0, s1>>>(x);
    cudaEventRecord(eJoin, s1);

    prep_b       <<<dim3(NPIX / 256, 128),       256>>>(qm, km);
    qk3x_kernel  <<<dim3(4, BATCH),              256, 65536>>>(x);
    energy_mma   <<<dim3(4, 4, BATCH),           256, 67584>>>(vb);
    reduce_kernel<<<dim3(BATCH * CCH / 256),     256>>>();

    cudaStreamWaitEvent(0, eJoin, 0);
    gemm_f16<<<dim3(CCH / 128,  CCH / 128, BATCH), 256, 65536>>>(0, nullptr);
    gemm_f16<<<dim3(NPIX / 128, CCH / 128, BATCH), 256, 65536>>>(1, out);
}

// round 16
// speedup vs baseline: 1.3645x; 1.0718x over previous
#include <cuda_runtime.h>
#include <cuda_fp16.h>
#include <cstdint>
#include <math.h>

#define BATCH 64
#define CCH   512
#define NPIX  1024
#define DD    64

// ---------------- scratch ----------------
__device__ __align__(128) float  g_q [BATCH * CCH * DD];
__device__ __align__(128) float  g_k [BATCH * CCH * DD];
__device__ __align__(128) __half g_at_h[(size_t)BATCH * CCH * CCH]; // unnorm T, half
__device__ __align__(128) __half g_m_h [(size_t)BATCH * CCH * CCH]; // M, half
__device__ __align__(128) float  g_ab[BATCH * CCH];
__device__ __align__(128) float  g_inv[BATCH * CCH];
__device__ __align__(128) float  g_ps [BATCH * CCH * 4];
__device__ __align__(128) float  g_psb[BATCH * CCH * 4];
__device__ __align__(128) __half g_wt_h[CCH * CCH];                  // W^T half
__device__ __align__(128) __half g_xt_h[(size_t)BATCH * NPIX * CCH]; // x^T half
__device__ __align__(128) __half g_bhi_h[128 * NPIX];                // [Qm^T;Km^T] hi
__device__ __align__(128) __half g_blo_h[128 * NPIX];                // lo

// ---------------- helpers ----------------
__device__ __forceinline__ uint32_t smem_u32(const void* p) {
    uint32_t a;
    asm("{ .reg .u64 t; cvta.to.shared.u64 t, %1; cvt.u32.u64 %0, t; }" : "=r"(a) : "l"(p));
    return a;
}
__device__ __forceinline__ void cpa16(uint32_t d, const void* g) {
    asm volatile("cp.async.cg.shared.global [%0], [%1], 16;" :: "r"(d), "l"(g) : "memory");
}
__device__ __forceinline__ void cpa_commit() {
    asm volatile("cp.async.commit_group;" ::: "memory");
}
__device__ __forceinline__ void mma_f16(float* c, const uint32_t* a, const uint32_t* b) {
    asm volatile(
        "mma.sync.aligned.m16n8k16.row.col.f32.f16.f16.f32 "
        "{%0,%1,%2,%3}, {%4,%5,%6,%7}, {%8,%9}, {%0,%1,%2,%3};"
        : "+f"(c[0]), "+f"(c[1]), "+f"(c[2]), "+f"(c[3])
        : "r"(a[0]), "r"(a[1]), "r"(a[2]), "r"(a[3]), "r"(b[0]), "r"(b[1]));
}
__device__ __forceinline__ void ldsm_x4(uint32_t* r, uint32_t addr) {
    asm volatile("ldmatrix.sync.aligned.m8n8.x4.shared.b16 {%0,%1,%2,%3}, [%4];"
        : "=r"(r[0]), "=r"(r[1]), "=r"(r[2]), "=r"(r[3]) : "r"(addr));
}
__device__ __forceinline__ void ldsm_x2(uint32_t* r, uint32_t addr) {
    asm volatile("ldmatrix.sync.aligned.m8n8.x2.shared.b16 {%0,%1}, [%2];"
        : "=r"(r[0]), "=r"(r[1]) : "r"(addr));
}
__device__ __forceinline__ uint32_t pack2(__half a, __half b) {
    __half2 t = __halves2half2(a, b);
    return *reinterpret_cast<uint32_t*>(&t);
}
__device__ __forceinline__ uint32_t ldsm32(const __half* p) {
    return *reinterpret_cast<const uint32_t*>(p);
}

// ============================================================================
// prep_b: half hi/lo planes of [Qm^T; Km^T]
// ============================================================================
__global__ __launch_bounds__(256) void prep_b(
    const float* __restrict__ qm, const float* __restrict__ km)
{
    const int n = blockIdx.x * 256 + threadIdx.x;
    const int d = blockIdx.y;
    float v = (d < 64) ? qm[n * 64 + d] : km[n * 64 + (d - 64)];
    __half h = __float2half_rn(v);
    g_bhi_h[d * NPIX + n] = h;
    g_blo_h[d * NPIX + n] = __float2half_rn(v - __half2float(h));
}

// ============================================================================
// qk3x fp16 + ldmatrix: [q|k] = x @ [Qm|Km], 3-pass hi/lo, BK=32 halves.
// smem buffer (bytes): Ah@0 Al@8192 Bh@16384 Bl@24576; x2 buffers = 64KB.
// Row = 64B = 4 chunks; swizzle ch ^ ((row>>1)&3). grid (4, BATCH). 2 CTA/SM.
// ============================================================================
__global__ __launch_bounds__(256, 2) void qk3x_kernel(const float* __restrict__ x)
{
    extern __shared__ __align__(16) __half qs[];
    const int b = blockIdx.y;
    const int row0 = blockIdx.x * 128;
    const float* Ab = x + (size_t)b * CCH * NPIX + (size_t)row0 * NPIX;

    const int tid = threadIdx.x;
    const int wid = tid >> 5, lid = tid & 31;
    const int gid = lid >> 2, tig = lid & 3;
    const int wm = wid >> 2, wn = wid & 3;

    const uint32_t sb = smem_u32(qs);
    const int row_st = tid >> 1, hh = tid & 1;
    const int asw = (row_st >> 1) & 3;

    // ldmatrix lane roles
    const int a_sel  = lid >> 3;                       // 0..3
    const int a_rof  = ((a_sel & 1) << 3) + (lid & 7); // row offset within 16
    const int a_cpar = a_sel >> 1;                     // chunk parity
    const int b_nof  = lid & 7;
    const int b_cpar = (lid >> 3) & 1;

    float4 va[4];
    auto ldgA = [&](int s) {
        const int k0 = s * 32;
#pragma unroll
        for (int q = 0; q < 4; q++)
            va[q] = *(const float4*)&Ab[(size_t)row_st * NPIX + k0 + hh * 16 + q * 4];
    };
    auto stsA = [&](int buf) {
        __half hv[16], lv[16];
#pragma unroll
        for (int q = 0; q < 4; q++) {
            const float f[4] = {va[q].x, va[q].y, va[q].z, va[q].w};
#pragma unroll
            for (int c = 0; c < 4; c++) {
                __half h = __float2half_rn(f[c]);
                hv[q * 4 + c] = h;
                lv[q * 4 + c] = __float2half_rn(f[c] - __half2float(h));
            }
        }
        const int base = buf * 16384 + row_st * 32;
        const int c0 = (2 * hh) ^ asw, c1 = (2 * hh + 1) ^ asw;
        *(uint4*)&qs[base + c0 * 8] = make_uint4(
            pack2(hv[0], hv[1]), pack2(hv[2], hv[3]), pack2(hv[4], hv[5]), pack2(hv[6], hv[7]));
        *(uint4*)&qs[base + c1 * 8] = make_uint4(
            pack2(hv[8], hv[9]), pack2(hv[10], hv[11]), pack2(hv[12], hv[13]), pack2(hv[14], hv[15]));
        *(uint4*)&qs[base + 4096 + c0 * 8] = make_uint4(
            pack2(lv[0], lv[1]), pack2(lv[2], lv[3]), pack2(lv[4], lv[5]), pack2(lv[6], lv[7]));
        *(uint4*)&qs[base + 4096 + c1 * 8] = make_uint4(
            pack2(lv[8], lv[9]), pack2(lv[10], lv[11]), pack2(lv[12], lv[13]), pack2(lv[14], lv[15]));
    };
    auto cpaB = [&](int s, int buf) {
        const int k0 = s * 32;
        const int c2 = hh * 2;
#pragma unroll
        for (int p = 0; p < 2; p++) {
            const int off = (p == 0) ? 8192 : 12288;
            const __half* src = (p == 0) ? g_bhi_h : g_blo_h;
#pragma unroll
            for (int ci = 0; ci < 2; ci++) {
                const int c = c2 + ci;
                const int cs = c ^ asw;
                cpa16(sb + (uint32_t)(buf * 16384 + off + row_st * 32 + cs * 8) * 2,
                      src + row_st * NPIX + k0 + c * 8);
            }
        }
        cpa_commit();
    };

    float acc[4][4][4] = {};
    int mrow[4], ncol[4];
#pragma unroll
    for (int i = 0; i < 4; i++) {
        mrow[i] = wm * 64 + i * 16 + gid;
        ncol[i] = wn * 32 + i * 8 + gid;
    }

    ldgA(0);
    cpaB(0, 0);
    stsA(0);

    for (int s = 0; s < 32; s++) {
        const int buf = s & 1;
        asm volatile("cp.async.wait_group 0;" ::: "memory");
        __syncthreads();
        if (s < 31) { ldgA(s + 1); cpaB(s + 1, buf ^ 1); }

        const uint32_t sbuf = sb + (uint32_t)buf * 32768u;  // byte base
#pragma unroll
        for (int ks = 0; ks < 2; ks++) {
            uint32_t ah[4][4], al[4][4];
#pragma unroll
            for (int mi = 0; mi < 4; mi++) {
                const int arow = wm * 64 + mi * 16 + a_rof;
                const int ch = (2 * ks + a_cpar) ^ ((arow >> 1) & 3);
                const uint32_t ad = sbuf + (uint32_t)(arow * 64 + ch * 16);
                ldsm_x4(ah[mi], ad);
                ldsm_x4(al[mi], ad + 8192u);
            }
#pragma unroll
            for (int ni = 0; ni < 4; ni++) {
                const int brow = wn * 32 + ni * 8 + b_nof;
                const int ch = (2 * ks + b_cpar) ^ ((brow >> 1) & 3);
                const uint32_t bd = sbuf + 16384u + (uint32_t)(brow * 64 + ch * 16);
                uint32_t bh[2], bl[2];
                ldsm_x2(bh, bd);
                ldsm_x2(bl, bd + 8192u);
#pragma unroll
                for (int mi = 0; mi < 4; mi++) {
                    mma_f16(acc[mi][ni], ah[mi], bh);
                    mma_f16(acc[mi][ni], ah[mi], bl);
                    mma_f16(acc[mi][ni], al[mi], bh);
                }
            }
        }
        __syncthreads();
        if (s < 31) stsA(buf ^ 1);
    }

    // epilogue: cols <64 -> g_q, >=64 -> g_k (fp32 for exact recompute)
#pragma unroll
    for (int mi = 0; mi < 4; mi++) {
        const int r1 = row0 + wm * 64 + mi * 16 + gid;
        const int r2 = r1 + 8;
#pragma unroll
        for (int ni = 0; ni < 4; ni++) {
            const int d = wn * 32 + ni * 8 + tig * 2;
            float* base = (d < 64) ? g_q : g_k;
            const int dc = d & 63;
            float* p1 = base + ((size_t)b * CCH + r1) * DD + dc;
            float* p2 = base + ((size_t)b * CCH + r2) * DD + dc;
            *(float2*)p1 = make_float2(acc[mi][ni][0], acc[mi][ni][1]);
            *(float2*)p2 = make_float2(acc[mi][ni][2], acc[mi][ni][3]);
        }
    }
}

// ============================================================================
// energy_mma fp16 (unchanged from R15): single-pass f16 MMA; saturate;
// exact recompute |e|<16. grid (4,4,64). smem 67584 B. 2 CTA/SM.
// ============================================================================
#define E_CONST 2.71828182845904523536f

__global__ __launch_bounds__(256, 2) void energy_mma(const float* __restrict__ vb)
{
    extern __shared__ __align__(16) float es[];
    __half* smh = (__half*)es;
    const int b  = blockIdx.z;
    const int j0 = blockIdx.x * 128;
    const int i0 = blockIdx.y * 128;
    const float* Q = g_q + ((size_t)b * CCH + i0) * DD;
    const float* K = g_k + ((size_t)b * CCH + j0) * DD;

    const int tid = threadIdx.x;
    const int wid = tid >> 5, lid = tid & 31;
    const int gid = lid >> 2, tig = lid & 3;
    const int wm = wid >> 2, wn = wid & 3;

    {
        const int row = tid >> 1, hh = tid & 1;
        const int rsw = row & 7;
#pragma unroll
        for (int m = 0; m < 2; m++) {
            const float* src = (m == 0) ? Q : K;
            __half* dst = smh + m * 8192;
            __half hv[32];
#pragma unroll
            for (int i = 0; i < 8; i++) {
                float4 v = *(const float4*)&src[(size_t)row * DD + hh * 32 + i * 4];
                hv[i * 4 + 0] = __float2half_rn(v.x);
                hv[i * 4 + 1] = __float2half_rn(v.y);
                hv[i * 4 + 2] = __float2half_rn(v.z);
                hv[i * 4 + 3] = __float2half_rn(v.w);
            }
#pragma unroll
            for (int i = 0; i < 4; i++) {
                const int c = hh * 4 + i;
                const int cs = c ^ rsw;
                *(uint4*)&dst[row * 64 + cs * 8] = make_uint4(
                    pack2(hv[i*8+0], hv[i*8+1]), pack2(hv[i*8+2], hv[i*8+3]),
                    pack2(hv[i*8+4], hv[i*8+5]), pack2(hv[i*8+6], hv[i*8+7]));
            }
        }
    }
    __syncthreads();

    float acc[4][4][4] = {};
    int mrow[4], ncol[4];
#pragma unroll
    for (int i = 0; i < 4; i++) {
        mrow[i] = wm * 64 + i * 16 + gid;
        ncol[i] = wn * 32 + i * 8 + gid;
    }

    const __half* qh = smh;
    const __half* kh = smh + 8192;
#pragma unroll
    for (int ks = 0; ks < 4; ks++) {
        uint32_t af[4][4], bf[4][2];
#pragma unroll
        for (int mi = 0; mi < 4; mi++) {
            const int r1 = mrow[mi], r2 = r1 + 8;
            af[mi][0] = ldsm32(qh + r1 * 64 + ((2*ks)   ^ (r1 & 7)) * 8 + 2 * tig);
            af[mi][1] = ldsm32(qh + r2 * 64 + ((2*ks)   ^ (r2 & 7)) * 8 + 2 * tig);
            af[mi][2] = ldsm32(qh + r1 * 64 + ((2*ks+1) ^ (r1 & 7)) * 8 + 2 * tig);
            af[mi][3] = ldsm32(qh + r2 * 64 + ((2*ks+1) ^ (r2 & 7)) * 8 + 2 * tig);
        }
#pragma unroll
        for (int ni = 0; ni < 4; ni++) {
            const int cc = ncol[ni];
            bf[ni][0] = ldsm32(kh + cc * 64 + ((2*ks)   ^ (cc & 7)) * 8 + 2 * tig);
            bf[ni][1] = ldsm32(kh + cc * 64 + ((2*ks+1) ^ (cc & 7)) * 8 + 2 * tig);
        }
#pragma unroll
        for (int mi = 0; mi < 4; mi++)
#pragma unroll
            for (int ni = 0; ni < 4; ni++)
                mma_f16(acc[mi][ni], af[mi], bf[ni]);
    }

    auto xf = [&](float e, int gi, int gj) -> float {
        if (fabsf(e) < 16.0f) {
            const float* qr = g_q + ((size_t)b * CCH + gi) * DD;
            const float* kr = g_k + ((size_t)b * CCH + gj) * DD;
            float s = 0.0f;
#pragma unroll
            for (int d = 0; d < DD; d += 4) {
                float4 a4 = *(const float4*)&qr[d];
                float4 b4 = *(const float4*)&kr[d];
                s += a4.x * b4.x + a4.y * b4.y + a4.z * b4.z + a4.w * b4.w;
            }
            float sg = 1.0f / (1.0f + __expf(-s));
            return __expf(sg);
        }
        return (e > 0.0f) ? E_CONST : 1.0f;
    };
#pragma unroll
    for (int mi = 0; mi < 4; mi++) {
        const int r1 = mrow[mi], r2 = r1 + 8;
#pragma unroll
        for (int ni = 0; ni < 4; ni++) {
            const int cc = wn * 32 + ni * 8 + tig * 2;
            acc[mi][ni][0] = xf(acc[mi][ni][0], i0 + r1, j0 + cc);
            acc[mi][ni][1] = xf(acc[mi][ni][1], i0 + r1, j0 + cc + 1);
            acc[mi][ni][2] = xf(acc[mi][ni][2], i0 + r2, j0 + cc);
            acc[mi][ni][3] = xf(acc[mi][ni][3], i0 + r2, j0 + cc + 1);
        }
    }

    __syncthreads();
#pragma unroll
    for (int mi = 0; mi < 4; mi++) {
        const int r1 = mrow[mi], r2 = r1 + 8;
#pragma unroll
        for (int ni = 0; ni < 4; ni++) {
            const int cc = wn * 32 + ni * 8 + tig * 2;
            es[(cc + 0) * 132 + r1] = acc[mi][ni][0];
            es[(cc + 1) * 132 + r1] = acc[mi][ni][1];
            es[(cc + 0) * 132 + r2] = acc[mi][ni][2];
            es[(cc + 1) * 132 + r2] = acc[mi][ni][3];
        }
    }
    __syncthreads();

    const int jj = tid >> 1;
    const int half_i = (tid & 1) * 64;
    __half* dst = g_at_h + ((size_t)b * CCH + j0 + jj) * CCH + i0 + half_i;
    float s = 0.0f, sb2 = 0.0f;
#pragma unroll
    for (int w = 0; w < 8; w++) {
        float4 v0 = *(float4*)&es[jj * 132 + half_i + w * 8];
        float4 v1 = *(float4*)&es[jj * 132 + half_i + w * 8 + 4];
        const float* bb = &vb[i0 + half_i + w * 8];
        s   += v0.x + v0.y + v0.z + v0.w + v1.x + v1.y + v1.z + v1.w;
        sb2 += v0.x*bb[0] + v0.y*bb[1] + v0.z*bb[2] + v0.w*bb[3]
             + v1.x*bb[4] + v1.y*bb[5] + v1.z*bb[6] + v1.w*bb[7];
        *(uint4*)&dst[w * 8] = make_uint4(
            pack2(__float2half_rn(v0.x), __float2half_rn(v0.y)),
            pack2(__float2half_rn(v0.z), __float2half_rn(v0.w)),
            pack2(__float2half_rn(v1.x), __float2half_rn(v1.y)),
            pack2(__float2half_rn(v1.z), __float2half_rn(v1.w)));
    }
    s   += __shfl_xor_sync(0xffffffffu, s,   1);
    sb2 += __shfl_xor_sync(0xffffffffu, sb2, 1);
    if ((tid & 1) == 0) {
        const int idx = ((b << 9) + j0 + jj) * 4 + blockIdx.y;
        g_ps[idx]  = s;
        g_psb[idx] = sb2;
    }
}

// ============================================================================
// reduce
// ============================================================================
__global__ __launch_bounds__(256) void reduce_kernel()
{
    const int idx = blockIdx.x * 256 + threadIdx.x;
    float S = 0.0f, TB = 0.0f;
#pragma unroll
    for (int r = 0; r < 4; r++) { S += g_ps[idx * 4 + r]; TB += g_psb[idx * 4 + r]; }
    g_inv[idx] = 1.0f / S;
    g_ab[idx]  = TB / S;
}

// ============================================================================
// Transposes (half outputs)
// ============================================================================
__global__ __launch_bounds__(256) void wt_kernel(const float* __restrict__ W)
{
    __shared__ float t[32][33];
    const int x0 = blockIdx.x * 32, y0 = blockIdx.y * 32;
    const int tx = threadIdx.x, ty = threadIdx.y;
#pragma unroll
    for (int r = 0; r < 32; r += 8) t[ty + r][tx] = W[(y0 + ty + r) * CCH + x0 + tx];
    __syncthreads();
#pragma unroll
    for (int r = 0; r < 32; r += 8)
        g_wt_h[(x0 + ty + r) * CCH + y0 + tx] = __float2half_rn(t[tx][ty + r]);
}

__global__ __launch_bounds__(256) void xt_kernel(const float* __restrict__ x)
{
    __shared__ float t[32][33];
    const int b = blockIdx.z;
    const float* in = x + (size_t)b * CCH * NPIX;
    __half* out = g_xt_h + (size_t)b * NPIX * CCH;
    const int n0 = blockIdx.x * 32, c0 = blockIdx.y * 32;
    const int tx = threadIdx.x, ty = threadIdx.y;
#pragma unroll
    for (int r = 0; r < 32; r += 8) t[ty + r][tx] = in[(size_t)(c0 + ty + r) * NPIX + n0 + tx];
    __syncthreads();
#pragma unroll
    for (int r = 0; r < 32; r += 8)
        out[(size_t)(n0 + ty + r) * CCH + c0 + tx] = __float2half_rn(t[tx][ty + r]);
}

// ============================================================================
// gemm fp16 + ldmatrix: 128x128 tile, BK=64 halves, double buffer, 2 CTA/SM.
// Row = 128B = 8 chunks; swizzle ch ^ (row&7).
// which==0: g_m_h = half((g_at_h @ g_wt_h) * (1/S_j))
// which==1: out   = (g_m_h @ g_xt_h) + ab     (fp32 out)
// ============================================================================
__global__ __launch_bounds__(256, 2) void gemm_f16(int which, float* __restrict__ outp)
{
    extern __shared__ __align__(16) __half sm[];

    const int b = blockIdx.z;
    const int col0 = blockIdx.x * 128, row0 = blockIdx.y * 128;

    const __half* A; const __half* B; __half* Ch = nullptr; float* Cf = nullptr; int ldc;
    if (which == 0) {
        A = g_at_h + (size_t)b * CCH * CCH;
        B = g_wt_h;
        Ch = g_m_h + (size_t)b * CCH * CCH;
        ldc = CCH;
    } else {
        A = g_m_h + (size_t)b * CCH * CCH;
        B = g_xt_h + (size_t)b * NPIX * CCH;
        Cf = outp + (size_t)b * CCH * NPIX;
        ldc = NPIX;
    }
    const __half* Ab = A + (size_t)row0 * CCH;
    const __half* Bb = B + (size_t)col0 * CCH;

    const int tid = threadIdx.x;
    const int wid = tid >> 5, lid = tid & 31;
    const int gid = lid >> 2, tig = lid & 3;
    const int wm = wid >> 2, wn = wid & 3;

    const uint32_t sb = smem_u32(sm);
    const int row_c = tid >> 1, hh = tid & 1;
    const int csw = row_c & 7;

    const int a_sel  = lid >> 3;
    const int a_rof  = ((a_sel & 1) << 3) + (lid & 7);
    const int a_cpar = a_sel >> 1;
    const int b_nof  = lid & 7;
    const int b_cpar = (lid >> 3) & 1;

    auto issue = [&](int s, int buf) {
        const int k0 = s * 64;
#pragma unroll
        for (int i = 0; i < 4; i++) {
            const int c = hh * 4 + i;
            const int cs = c ^ csw;
            cpa16(sb + (uint32_t)(buf * 16384 + row_c * 64 + cs * 8) * 2,
                  Ab + (size_t)row_c * CCH + k0 + c * 8);
            cpa16(sb + (uint32_t)(buf * 16384 + 8192 + row_c * 64 + cs * 8) * 2,
                  Bb + (size_t)row_c * CCH + k0 + c * 8);
        }
        cpa_commit();
    };

    float acc[4][4][4] = {};
    int mrow[4], ncol[4];
#pragma unroll
    for (int i = 0; i < 4; i++) {
        mrow[i] = wm * 64 + i * 16 + gid;
        ncol[i] = wn * 32 + i * 8 + gid;
    }

    issue(0, 0);

    for (int s = 0; s < 8; s++) {
        const int buf = s & 1;
        if (s < 7) issue(s + 1, buf ^ 1);
        if (s < 7) { asm volatile("cp.async.wait_group 1;" ::: "memory"); }
        else       { asm volatile("cp.async.wait_group 0;" ::: "memory"); }
        __syncthreads();

        const uint32_t sbuf = sb + (uint32_t)buf * 32768u;  // byte base
#pragma unroll
        for (int ks = 0; ks < 4; ks++) {
            uint32_t af[4][4];
#pragma unroll
            for (int mi = 0; mi < 4; mi++) {
                const int arow = wm * 64 + mi * 16 + a_rof;
                const int ch = (2 * ks + a_cpar) ^ (arow & 7);
                ldsm_x4(af[mi], sbuf + (uint32_t)(arow * 128 + ch * 16));
            }
#pragma unroll
            for (int ni = 0; ni < 4; ni++) {
                const int brow = wn * 32 + ni * 8 + b_nof;
                const int ch = (2 * ks + b_cpar) ^ (brow & 7);
                uint32_t bf[2];
                ldsm_x2(bf, sbuf + 16384u + (uint32_t)(brow * 128 + ch * 16));
#pragma unroll
                for (int mi = 0; mi < 4; mi++)
                    mma_f16(acc[mi][ni], af[mi], bf);
            }
        }
        __syncthreads();
    }

    // epilogue
#pragma unroll
    for (int mi = 0; mi < 4; mi++) {
        const int r1 = row0 + wm * 64 + mi * 16 + gid;
        const int r2 = r1 + 8;
        float s1, s2;
        if (which == 0) { s1 = g_inv[(b << 9) + r1]; s2 = g_inv[(b << 9) + r2]; }
        else            { s1 = g_ab [(b << 9) + r1]; s2 = g_ab [(b << 9) + r2]; }
#pragma unroll
        for (int ni = 0; ni < 4; ni++) {
            const int cc = col0 + wn * 32 + ni * 8 + tig * 2;
            float c0 = acc[mi][ni][0], c1 = acc[mi][ni][1];
            float c2 = acc[mi][ni][2], c3 = acc[mi][ni][3];
            if (which == 0) {
                *(uint32_t*)&Ch[(size_t)r1 * ldc + cc] =
                    pack2(__float2half_rn(c0 * s1), __float2half_rn(c1 * s1));
                *(uint32_t*)&Ch[(size_t)r2 * ldc + cc] =
                    pack2(__float2half_rn(c2 * s2), __float2half_rn(c3 * s2));
            } else {
                *(float2*)&Cf[(size_t)r1 * ldc + cc] = make_float2(c0 + s1, c1 + s1);
                *(float2*)&Cf[(size_t)r2 * ldc + cc] = make_float2(c2 + s2, c3 + s2);
            }
        }
    }
}

// ============================================================================
// kernel_launch: forked-stream capture (wt, xt on side stream).
// ============================================================================
extern "C" void kernel_launch(void* const* d_in, const int* in_sizes, int n_in,
                              void* d_out, int out_size)
{
    const float* x  = (const float*)d_in[0];
    const float* qm = (const float*)d_in[1];
    const float* km = (const float*)d_in[2];
    const float* vw = (const float*)d_in[3];
    const float* vb = (const float*)d_in[4];
    float* out = (float*)d_out;

    cudaFuncSetAttribute(gemm_f16,    cudaFuncAttributeMaxDynamicSharedMemorySize, 65536);
    cudaFuncSetAttribute(qk3x_kernel, cudaFuncAttributeMaxDynamicSharedMemorySize, 65536);
    cudaFuncSetAttribute(energy_mma,  cudaFuncAttributeMaxDynamicSharedMemorySize, 67584);

    cudaStream_t s1;
    cudaEvent_t eFork, eJoin;
    cudaStreamCreateWithFlags(&s1, cudaStreamNonBlocking);
    cudaEventCreateWithFlags(&eFork, cudaEventDisableTiming);
    cudaEventCreateWithFlags(&eJoin, cudaEventDisableTiming);

    cudaEventRecord(eFork, 0);
    cudaStreamWaitEvent(s1, eFork, 0);
    wt_kernel<<<dim3(16, 16),        dim3(32, 8), 0, s1>>>(vw);
    xt_kernel<<<dim3(32, 16, BATCH), dim3(32, 8), 0, s1>>>(x);
    cudaEventRecord(eJoin, s1);

    prep_b       <<<dim3(NPIX / 256, 128),       256>>>(qm, km);
    qk3x_kernel  <<<dim3(4, BATCH),              256, 65536>>>(x);
    energy_mma   <<<dim3(4, 4, BATCH),           256, 67584>>>(vb);
    reduce_kernel<<<dim3(BATCH * CCH / 256),     256>>>();

    cudaStreamWaitEvent(0, eJoin, 0);
    gemm_f16<<<dim3(CCH / 128,  CCH / 128, BATCH), 256, 65536>>>(0, nullptr);
    gemm_f16<<<dim3(NPIX / 128, CCH / 128, BATCH), 256, 65536>>>(1, out);
}